// round 5
// baseline (speedup 1.0000x reference)
#include <cuda_runtime.h>
#include <math.h>
#include <stdint.h>

#define B_  2
#define S_  2048
#define D_  1024
#define H_  16
#define W_  64
#define M_  (B_ * S_)

// Scratch (tf32-rounded fp32 bit patterns):
// g_q: [B,H,S,W], pre-scaled by 0.125, plain layout
// g_k: [B,H,S,W], w permuted within 8-blocks: pos = 2*(w&3) + ((w>>2)&1)
// g_v: [B,H,W,S] (transposed), s permuted within 8-blocks (same perm)
__device__ float g_q[B_ * H_ * S_ * W_];
__device__ float g_k[B_ * H_ * S_ * W_];
__device__ float g_v[B_ * H_ * S_ * W_];

// ---------------------------------------------------------------------------
__device__ __forceinline__ float tf32f(float x) {
    uint32_t u;
    asm("cvt.rna.tf32.f32 %0, %1;" : "=r"(u) : "f"(x));
    return __uint_as_float(u);
}
__device__ __forceinline__ void mma_tf32(float c[4], const uint32_t a[4], const uint32_t b[2]) {
    asm volatile(
        "mma.sync.aligned.m16n8k8.row.col.f32.tf32.tf32.f32 "
        "{%0,%1,%2,%3}, {%4,%5,%6,%7}, {%8,%9}, {%0,%1,%2,%3};"
        : "+f"(c[0]), "+f"(c[1]), "+f"(c[2]), "+f"(c[3])
        : "r"(a[0]), "r"(a[1]), "r"(a[2]), "r"(a[3]), "r"(b[0]), "r"(b[1]));
}

// ---------------------------------------------------------------------------
// QKV projection GEMM via mma.sync tf32 (R3-proven mainloop; scalar epilogue).
// ---------------------------------------------------------------------------
#define BK 16
#define AST 136
#define TBUF (BK * AST)
#define AIDX(k, m) ((k) * AST + ((m) ^ ((((k) >> 2) & 3) << 3)))

__global__ __launch_bounds__(256) void qkv_gemm(
    const float* __restrict__ X,
    const float* __restrict__ Wq_, const float* __restrict__ Wk_, const float* __restrict__ Wv_,
    const float* __restrict__ bq, const float* __restrict__ bk, const float* __restrict__ bv,
    float* __restrict__ outq, float* __restrict__ outk, float* __restrict__ outv)
{
    extern __shared__ float smg[];
    const int tid = threadIdx.x;
    const int lane = tid & 31;
    const int wid = tid >> 5;
    const int wm = wid & 3, wn = wid >> 2;
    const int lt = lane & 3, lg = lane >> 2;
    const int n0 = blockIdx.x * 128;
    const int m0 = blockIdx.y * 128;
    const int z = blockIdx.z;
    const float* W = z == 0 ? Wq_ : (z == 1 ? Wk_ : Wv_);
    const float* bias = z == 0 ? bq : (z == 1 ? bk : bv);

    float acc[2][8][4];
#pragma unroll
    for (int f = 0; f < 2; f++)
#pragma unroll
        for (int nb = 0; nb < 8; nb++)
#pragma unroll
            for (int j = 0; j < 4; j++) acc[f][nb][j] = 0.0f;

    float4 ra[2], rb[2];
    const int a_row0 = tid >> 2;
    const int a_kq = tid & 3;
    const int b_kr0 = tid >> 5;
    const int b_nq = tid & 31;

#define LDG_TILE(c)                                                                 \
    {                                                                               \
        int kk = (c) * BK;                                                          \
        _Pragma("unroll")                                                           \
        for (int i = 0; i < 2; i++) {                                               \
            ra[i] = *(const float4*)(X + (size_t)(m0 + a_row0 + i * 64) * D_ + kk + a_kq * 4); \
            rb[i] = *(const float4*)(W + (size_t)(kk + b_kr0 + i * 8) * D_ + n0 + b_nq * 4);   \
        }                                                                           \
    }

#define STS_TILE(buf)                                                               \
    {                                                                               \
        float* As = smg + (buf) * 2 * TBUF;                                         \
        float* Bs = As + TBUF;                                                      \
        _Pragma("unroll")                                                           \
        for (int i = 0; i < 2; i++) {                                               \
            int row = a_row0 + i * 64;                                              \
            float av[4] = {ra[i].x, ra[i].y, ra[i].z, ra[i].w};                     \
            _Pragma("unroll")                                                       \
            for (int j = 0; j < 4; j++) As[AIDX(a_kq * 4 + j, row)] = tf32f(av[j]); \
            int kr = b_kr0 + i * 8;                                                 \
            float4 t;                                                               \
            t.x = tf32f(rb[i].x); t.y = tf32f(rb[i].y);                             \
            t.z = tf32f(rb[i].z); t.w = tf32f(rb[i].w);                             \
            *(float4*)&Bs[kr * AST + ((b_nq * 4) ^ ((((kr) >> 2) & 3) << 3))] = t;  \
        }                                                                           \
    }

    LDG_TILE(0);
    STS_TILE(0);

    const int NITER = D_ / BK;
    for (int c = 0; c < NITER; c++) {
        __syncthreads();
        if (c + 1 < NITER) LDG_TILE(c + 1);
        const float* As = smg + (c & 1) * 2 * TBUF;
        const float* Bs = As + TBUF;
#pragma unroll
        for (int t4 = 0; t4 < 2; t4++) {
            const int k8 = t4 * 8;
            uint32_t a[2][4];
#pragma unroll
            for (int f = 0; f < 2; f++) {
                const int mb = wm * 32 + f * 16;
                a[f][0] = __float_as_uint(As[AIDX(k8 + lt, mb + lg)]);
                a[f][1] = __float_as_uint(As[AIDX(k8 + lt, mb + lg + 8)]);
                a[f][2] = __float_as_uint(As[AIDX(k8 + lt + 4, mb + lg)]);
                a[f][3] = __float_as_uint(As[AIDX(k8 + lt + 4, mb + lg + 8)]);
            }
#pragma unroll
            for (int nb = 0; nb < 8; nb++) {
                const int nbb = wn * 64 + nb * 8;
                uint32_t b[2];
                b[0] = __float_as_uint(Bs[AIDX(k8 + lt, nbb + lg)]);
                b[1] = __float_as_uint(Bs[AIDX(k8 + lt + 4, nbb + lg)]);
                mma_tf32(acc[0][nb], a[0], b);
                mma_tf32(acc[1][nb], a[1], b);
            }
        }
        if (c + 1 < NITER) STS_TILE((c + 1) & 1);
    }

    // epilogue: bias + tf32 + per-tensor layout (all scalar stores)
#pragma unroll
    for (int f = 0; f < 2; f++) {
#pragma unroll
        for (int half = 0; half < 2; half++) {
            int m = m0 + wm * 32 + f * 16 + lg + half * 8;
            int b = m >> 11;
            int s = m & 2047;
#pragma unroll
            for (int nb = 0; nb < 8; nb++) {
                int n = n0 + wn * 64 + nb * 8 + lt * 2;
                int h = n >> 6, w = n & 63;
                float v0 = acc[f][nb][half * 2 + 0] + __ldg(&bias[n]);
                float v1 = acc[f][nb][half * 2 + 1] + __ldg(&bias[n + 1]);
                if (z == 0) {
                    size_t base = (((size_t)(b * H_ + h) * S_) + s) * W_;
                    outq[base + w]     = tf32f(v0 * 0.125f);
                    outq[base + w + 1] = tf32f(v1 * 0.125f);
                } else if (z == 1) {
                    int wl = w & 7;   // even
                    int p0 = 2 * (wl & 3) + ((wl >> 2) & 1);
                    int p1 = 2 * ((wl + 1) & 3) + (((wl + 1) >> 2) & 1);
                    size_t base = (((size_t)(b * H_ + h) * S_) + s) * W_ + (w & ~7);
                    outk[base + p0] = tf32f(v0);
                    outk[base + p1] = tf32f(v1);
                } else {
                    int sp = (s & ~7) | (2 * (s & 3)) | ((s >> 2) & 1);
                    size_t basev = (((size_t)(b * H_ + h) * W_ + w) * S_) + sp;
                    outv[basev]      = tf32f(v0);
                    outv[basev + S_] = tf32f(v1);
                }
            }
        }
    }
}

// ---------------------------------------------------------------------------
// Flash attention: 256 threads (8 warps x 16 query rows), BQ=128, Ktile=64.
// Q frags in registers; K/V single-buffered via float4 LDG->STS; LDS.64
// fragment loads via pair-permuted layouts; P in smem (warp-private rows).
// ---------------------------------------------------------------------------
#define KST 72
#define KVF (64 * KST)
#define ATTN_SMEM ((2 * KVF + 128 * KST) * 4)   // 73728 bytes

__global__ __launch_bounds__(256, 2) void attn_kernel(float* __restrict__ Out)
{
    extern __shared__ float sma[];
    float* Ks = sma;                 // [key][w_perm]
    float* Vs = sma + KVF;           // [w][key_perm]
    float* Ps = sma + 2 * KVF;       // [m][key_perm]

    const int tid = threadIdx.x;
    const int lane = tid & 31;
    const int wid = tid >> 5;
    const int lt = lane & 3, lg = lane >> 4 ? 0 : 0;   // placeholder (replaced below)
    const int lgr = lane >> 2;
    const int mb = wid * 16;
    const int q0 = blockIdx.x * 128;
    const int h = blockIdx.y, b = blockIdx.z;

    const float* qb = g_q + (size_t)(b * H_ + h) * S_ * W_;
    const float* kb = g_k + (size_t)(b * H_ + h) * S_ * W_;
    const float* vb = g_v + (size_t)(b * H_ + h) * W_ * S_;   // [W][S]

    // P store positions (permuted key slots)
    const int pA = 2 * ((2 * lt) & 3) + (((2 * lt) >> 2) & 1);
    const int pB = 2 * ((2 * lt + 1) & 3) + (((2 * lt + 1) >> 2) & 1);

    // Q fragments (already tf32 + scaled), plain layout
    uint32_t qf[8][4];
    {
        const float* q_r0 = qb + (size_t)(q0 + mb + lgr) * W_;
        const float* q_r1 = q_r0 + 8 * W_;
#pragma unroll
        for (int ks = 0; ks < 8; ks++) {
            qf[ks][0] = __float_as_uint(__ldg(q_r0 + ks * 8 + lt));
            qf[ks][1] = __float_as_uint(__ldg(q_r1 + ks * 8 + lt));
            qf[ks][2] = __float_as_uint(__ldg(q_r0 + ks * 8 + lt + 4));
            qf[ks][3] = __float_as_uint(__ldg(q_r1 + ks * 8 + lt + 4));
        }
    }

    float m0r = -INFINITY, m1r = -INFINITY, l0 = 0.0f, l1 = 0.0f;
    float oacc[8][4];
#pragma unroll
    for (int nb = 0; nb < 8; nb++)
#pragma unroll
        for (int j = 0; j < 4; j++) oacc[nb][j] = 0.0f;

    const int NT = S_ / 64;   // 32
    for (int j = 0; j < NT; j++) {
        const int j0 = j * 64;
        __syncthreads();   // prior reads of Ks/Vs complete
#pragma unroll
        for (int i = 0; i < 4; i++) {
            int u = i * 256 + tid;
            int r = u >> 4, c4 = (u & 15) * 4;
            *(float4*)&Ks[r * KST + c4] = *(const float4*)(kb + (size_t)(j0 + r) * W_ + c4);
            *(float4*)&Vs[r * KST + c4] = *(const float4*)(vb + (size_t)r * S_ + j0 + c4);
        }
        __syncthreads();

        // S = Q @ K^T  (16 x 64 per warp)
        float sacc[8][4];
#pragma unroll
        for (int nb = 0; nb < 8; nb++)
#pragma unroll
            for (int j2 = 0; j2 < 4; j2++) sacc[nb][j2] = 0.0f;

#pragma unroll
        for (int ks = 0; ks < 8; ks++) {
#pragma unroll
            for (int nb = 0; nb < 8; nb++) {
                float2 b2 = *(const float2*)&Ks[(nb * 8 + lgr) * KST + ks * 8 + 2 * lt];
                uint32_t bfr[2] = {__float_as_uint(b2.x), __float_as_uint(b2.y)};
                mma_tf32(sacc[nb], qf[ks], bfr);
            }
        }

        // online softmax (rows lgr, lgr+8 of warp tile)
        float mx0 = -INFINITY, mx1 = -INFINITY;
#pragma unroll
        for (int nb = 0; nb < 8; nb++) {
            mx0 = fmaxf(mx0, fmaxf(sacc[nb][0], sacc[nb][1]));
            mx1 = fmaxf(mx1, fmaxf(sacc[nb][2], sacc[nb][3]));
        }
        mx0 = fmaxf(mx0, __shfl_xor_sync(0xffffffffu, mx0, 1));
        mx0 = fmaxf(mx0, __shfl_xor_sync(0xffffffffu, mx0, 2));
        mx1 = fmaxf(mx1, __shfl_xor_sync(0xffffffffu, mx1, 1));
        mx1 = fmaxf(mx1, __shfl_xor_sync(0xffffffffu, mx1, 2));

        float mn0 = fmaxf(m0r, mx0), mn1 = fmaxf(m1r, mx1);
        float al0 = __expf(m0r - mn0), al1 = __expf(m1r - mn1);
        float s0 = 0.0f, s1 = 0.0f;
#pragma unroll
        for (int nb = 0; nb < 8; nb++) {
            float p0 = __expf(sacc[nb][0] - mn0);
            float p1 = __expf(sacc[nb][1] - mn0);
            float p2 = __expf(sacc[nb][2] - mn1);
            float p3 = __expf(sacc[nb][3] - mn1);
            sacc[nb][0] = p0; sacc[nb][1] = p1; sacc[nb][2] = p2; sacc[nb][3] = p3;
            s0 += p0 + p1;
            s1 += p2 + p3;
        }
        s0 += __shfl_xor_sync(0xffffffffu, s0, 1);
        s0 += __shfl_xor_sync(0xffffffffu, s0, 2);
        s1 += __shfl_xor_sync(0xffffffffu, s1, 1);
        s1 += __shfl_xor_sync(0xffffffffu, s1, 2);
        l0 = l0 * al0 + s0;
        l1 = l1 * al1 + s1;
        m0r = mn0; m1r = mn1;
#pragma unroll
        for (int nb = 0; nb < 8; nb++) {
            oacc[nb][0] *= al0; oacc[nb][1] *= al0;
            oacc[nb][2] *= al1; oacc[nb][3] *= al1;
        }

        // stage P (tf32, permuted key slots), warp-private rows
#pragma unroll
        for (int nb = 0; nb < 8; nb++) {
            Ps[(mb + lgr) * KST + nb * 8 + pA]     = tf32f(sacc[nb][0]);
            Ps[(mb + lgr) * KST + nb * 8 + pB]     = tf32f(sacc[nb][1]);
            Ps[(mb + lgr + 8) * KST + nb * 8 + pA] = tf32f(sacc[nb][2]);
            Ps[(mb + lgr + 8) * KST + nb * 8 + pB] = tf32f(sacc[nb][3]);
        }
        __syncwarp();

        // O += P @ V  (Vs = [w][key_perm])
#pragma unroll
        for (int ks = 0; ks < 8; ks++) {
            float2 a02 = *(const float2*)&Ps[(mb + lgr) * KST + ks * 8 + 2 * lt];
            float2 a13 = *(const float2*)&Ps[(mb + lgr + 8) * KST + ks * 8 + 2 * lt];
            uint32_t a[4] = {__float_as_uint(a02.x), __float_as_uint(a13.x),
                             __float_as_uint(a02.y), __float_as_uint(a13.y)};
#pragma unroll
            for (int nb = 0; nb < 8; nb++) {
                float2 b2 = *(const float2*)&Vs[(nb * 8 + lgr) * KST + ks * 8 + 2 * lt];
                uint32_t bfr[2] = {__float_as_uint(b2.x), __float_as_uint(b2.y)};
                mma_tf32(oacc[nb], a, bfr);
            }
        }
    }

    // epilogue: normalize, write [B,S,D] (float2, even offsets — R3-proven)
    const float inv0 = 1.0f / l0, inv1 = 1.0f / l1;
    const int r0 = q0 + mb + lgr;
    (void)lt; (void)lg;
#pragma unroll
    for (int nb = 0; nb < 8; nb++) {
        int w = nb * 8 + lt * 2;
        float2 v0, v1;
        v0.x = oacc[nb][0] * inv0; v0.y = oacc[nb][1] * inv0;
        v1.x = oacc[nb][2] * inv1; v1.y = oacc[nb][3] * inv1;
        *(float2*)&Out[((size_t)b * S_ + r0) * D_ + h * W_ + w] = v0;
        *(float2*)&Out[((size_t)b * S_ + r0 + 8) * D_ + h * W_ + w] = v1;
    }
}

// ---------------------------------------------------------------------------
extern "C" void kernel_launch(void* const* d_in, const int* in_sizes, int n_in,
                              void* d_out, int out_size)
{
    const float* x  = (const float*)d_in[0];
    const float* Wq = (const float*)d_in[1];
    const float* bq = (const float*)d_in[2];
    const float* Wk = (const float*)d_in[3];
    const float* bk = (const float*)d_in[4];
    const float* Wv = (const float*)d_in[5];
    const float* bv = (const float*)d_in[6];
    float* out = (float*)d_out;

    float *pq, *pk, *pv;
    cudaGetSymbolAddress((void**)&pq, g_q);
    cudaGetSymbolAddress((void**)&pk, g_k);
    cudaGetSymbolAddress((void**)&pv, g_v);

    const int gemm_smem = 2 * 2 * TBUF * (int)sizeof(float);
    dim3 ggrid(D_ / 128, M_ / 128, 3);
    qkv_gemm<<<ggrid, 256, gemm_smem>>>(x, Wq, Wk, Wv, bq, bk, bv, pq, pk, pv);

    cudaFuncSetAttribute(attn_kernel, cudaFuncAttributeMaxDynamicSharedMemorySize, ATTN_SMEM);
    dim3 attn_grid(S_ / 128, H_, B_);    // (16, 16, 2)
    attn_kernel<<<attn_grid, 256, ATTN_SMEM>>>(out);
}

// round 6
// speedup vs baseline: 1.4993x; 1.4993x over previous
#include <cuda_runtime.h>
#include <math.h>
#include <stdint.h>

#define B_  2
#define S_  2048
#define D_  1024
#define H_  16
#define W_  64
#define M_  (B_ * S_)

// Scratch (tf32-rounded fp32 bit patterns):
// g_q:  [B,H,S,W], pre-scaled by 0.125, w perm8'd within 8-blocks
// g_k:  [B,H,S,W], w perm8'd within 8-blocks
// g_v:  [B,H,S,W], plain (coalesced gemm epilogue)
// g_vt: [B,H,W,S], s perm8'd within 8-blocks (made by transpose kernel)
// perm8(x) = 2*(x&3) + ((x>>2)&1)
__device__ float g_q[B_ * H_ * S_ * W_];
__device__ float g_k[B_ * H_ * S_ * W_];
__device__ float g_v[B_ * H_ * S_ * W_];
__device__ float g_vt[B_ * H_ * S_ * W_];

// ---------------------------------------------------------------------------
__device__ __forceinline__ float tf32f(float x) {
    uint32_t u;
    asm("cvt.rna.tf32.f32 %0, %1;" : "=r"(u) : "f"(x));
    return __uint_as_float(u);
}
__device__ __forceinline__ void mma_tf32(float c[4], const uint32_t a[4], const uint32_t b[2]) {
    asm volatile(
        "mma.sync.aligned.m16n8k8.row.col.f32.tf32.tf32.f32 "
        "{%0,%1,%2,%3}, {%4,%5,%6,%7}, {%8,%9}, {%0,%1,%2,%3};"
        : "+f"(c[0]), "+f"(c[1]), "+f"(c[2]), "+f"(c[3])
        : "r"(a[0]), "r"(a[1]), "r"(a[2]), "r"(a[3]), "r"(b[0]), "r"(b[1]));
}

// ---------------------------------------------------------------------------
// QKV projection GEMM via mma.sync tf32 (R3-proven mainloop).
// ---------------------------------------------------------------------------
#define BK 16
#define AST 136
#define TBUF (BK * AST)
#define AIDX(k, m) ((k) * AST + ((m) ^ ((((k) >> 2) & 3) << 3)))

__global__ __launch_bounds__(256) void qkv_gemm(
    const float* __restrict__ X,
    const float* __restrict__ Wq_, const float* __restrict__ Wk_, const float* __restrict__ Wv_,
    const float* __restrict__ bq, const float* __restrict__ bk, const float* __restrict__ bv,
    float* __restrict__ outq, float* __restrict__ outk, float* __restrict__ outv)
{
    extern __shared__ float smg[];
    const int tid = threadIdx.x;
    const int lane = tid & 31;
    const int wid = tid >> 5;
    const int wm = wid & 3, wn = wid >> 2;
    const int lt = lane & 3, lg = lane >> 2;
    const int n0 = blockIdx.x * 128;
    const int m0 = blockIdx.y * 128;
    const int z = blockIdx.z;
    const float* W = z == 0 ? Wq_ : (z == 1 ? Wk_ : Wv_);
    const float* bias = z == 0 ? bq : (z == 1 ? bk : bv);

    float acc[2][8][4];
#pragma unroll
    for (int f = 0; f < 2; f++)
#pragma unroll
        for (int nb = 0; nb < 8; nb++)
#pragma unroll
            for (int j = 0; j < 4; j++) acc[f][nb][j] = 0.0f;

    float4 ra[2], rb[2];
    const int a_row0 = tid >> 2;
    const int a_kq = tid & 3;
    const int b_kr0 = tid >> 5;
    const int b_nq = tid & 31;

#define LDG_TILE(c)                                                                 \
    {                                                                               \
        int kk = (c) * BK;                                                          \
        _Pragma("unroll")                                                           \
        for (int i = 0; i < 2; i++) {                                               \
            ra[i] = *(const float4*)(X + (size_t)(m0 + a_row0 + i * 64) * D_ + kk + a_kq * 4); \
            rb[i] = *(const float4*)(W + (size_t)(kk + b_kr0 + i * 8) * D_ + n0 + b_nq * 4);   \
        }                                                                           \
    }

#define STS_TILE(buf)                                                               \
    {                                                                               \
        float* As = smg + (buf) * 2 * TBUF;                                         \
        float* Bs = As + TBUF;                                                      \
        _Pragma("unroll")                                                           \
        for (int i = 0; i < 2; i++) {                                               \
            int row = a_row0 + i * 64;                                              \
            float av[4] = {ra[i].x, ra[i].y, ra[i].z, ra[i].w};                     \
            _Pragma("unroll")                                                       \
            for (int j = 0; j < 4; j++) As[AIDX(a_kq * 4 + j, row)] = tf32f(av[j]); \
            int kr = b_kr0 + i * 8;                                                 \
            float4 t;                                                               \
            t.x = tf32f(rb[i].x); t.y = tf32f(rb[i].y);                             \
            t.z = tf32f(rb[i].z); t.w = tf32f(rb[i].w);                             \
            *(float4*)&Bs[kr * AST + ((b_nq * 4) ^ ((((kr) >> 2) & 3) << 3))] = t;  \
        }                                                                           \
    }

    LDG_TILE(0);
    STS_TILE(0);

    const int NITER = D_ / BK;
    for (int c = 0; c < NITER; c++) {
        __syncthreads();
        if (c + 1 < NITER) LDG_TILE(c + 1);
        const float* As = smg + (c & 1) * 2 * TBUF;
        const float* Bs = As + TBUF;
#pragma unroll
        for (int t4 = 0; t4 < 2; t4++) {
            const int k8 = t4 * 8;
            uint32_t a[2][4];
#pragma unroll
            for (int f = 0; f < 2; f++) {
                const int mb = wm * 32 + f * 16;
                a[f][0] = __float_as_uint(As[AIDX(k8 + lt, mb + lg)]);
                a[f][1] = __float_as_uint(As[AIDX(k8 + lt, mb + lg + 8)]);
                a[f][2] = __float_as_uint(As[AIDX(k8 + lt + 4, mb + lg)]);
                a[f][3] = __float_as_uint(As[AIDX(k8 + lt + 4, mb + lg + 8)]);
            }
#pragma unroll
            for (int nb = 0; nb < 8; nb++) {
                const int nbb = wn * 64 + nb * 8;
                uint32_t b[2];
                b[0] = __float_as_uint(Bs[AIDX(k8 + lt, nbb + lg)]);
                b[1] = __float_as_uint(Bs[AIDX(k8 + lt + 4, nbb + lg)]);
                mma_tf32(acc[0][nb], a[0], b);
                mma_tf32(acc[1][nb], a[1], b);
            }
        }
        if (c + 1 < NITER) STS_TILE((c + 1) & 1);
    }

    // epilogue: bias + tf32; Q/K perm8 scalar (same-sector), V coalesced float2
#pragma unroll
    for (int f = 0; f < 2; f++) {
#pragma unroll
        for (int half = 0; half < 2; half++) {
            int m = m0 + wm * 32 + f * 16 + lg + half * 8;
            int b = m >> 11;
            int s = m & 2047;
#pragma unroll
            for (int nb = 0; nb < 8; nb++) {
                int n = n0 + wn * 64 + nb * 8 + lt * 2;
                int h = n >> 6, w = n & 63;
                float v0 = acc[f][nb][half * 2 + 0] + __ldg(&bias[n]);
                float v1 = acc[f][nb][half * 2 + 1] + __ldg(&bias[n + 1]);
                int wl = w & 7;   // even
                int p0 = 2 * (wl & 3) + ((wl >> 2) & 1);
                int p1 = 2 * ((wl + 1) & 3) + (((wl + 1) >> 2) & 1);
                size_t base = (((size_t)(b * H_ + h) * S_) + s) * W_;
                if (z == 0) {
                    outq[base + (w & ~7) + p0] = tf32f(v0 * 0.125f);
                    outq[base + (w & ~7) + p1] = tf32f(v1 * 0.125f);
                } else if (z == 1) {
                    outk[base + (w & ~7) + p0] = tf32f(v0);
                    outk[base + (w & ~7) + p1] = tf32f(v1);
                } else {
                    float2 t;
                    t.x = tf32f(v0);
                    t.y = tf32f(v1);
                    *(float2*)&outv[base + w] = t;
                }
            }
        }
    }
}

// ---------------------------------------------------------------------------
// V transpose: [B,H,S,W] -> [B,H,W,S] with perm8 applied on the s (key) dim.
// ---------------------------------------------------------------------------
__global__ __launch_bounds__(256) void transpose_v(
    const float* __restrict__ Vin, float* __restrict__ Vt)
{
    __shared__ float t[32][33];
    const int bh = blockIdx.z;
    const int tx = threadIdx.x & 31;
    const int ty = threadIdx.x >> 5;     // 0..7
    const int w0 = blockIdx.x * 32;
    const int s0 = blockIdx.y * 32;
    const float* src = Vin + (size_t)bh * S_ * W_;
    float* dst = Vt + (size_t)bh * W_ * S_;
#pragma unroll
    for (int i = 0; i < 32; i += 8)
        t[ty + i][tx] = src[(size_t)(s0 + ty + i) * W_ + w0 + tx];
    __syncthreads();
    // write rows of [w][s]; col = s with perm8 within 8-block (same-sector)
    const int sp = (tx & ~7) | (2 * (tx & 3)) | ((tx >> 2) & 1);
#pragma unroll
    for (int i = 0; i < 32; i += 8)
        dst[(size_t)(w0 + ty + i) * S_ + s0 + sp] = t[tx][ty + i];
}

// ---------------------------------------------------------------------------
// Flash attention: 256 threads (8 warps x 16 query rows), BQ=128, Ktile=64.
// Q in smem (loaded once, pre-permuted); K/V single-buffered LDG->STS;
// all fragment loads are LDS.64 via perm8 layouts; P staged in smem.
// ---------------------------------------------------------------------------
#define KST 72
#define ATTN_SMEM (384 * KST * 4)   // Q128 + K64 + V64 + P128 rows = 110592 B

__global__ __launch_bounds__(256, 2) void attn_kernel(float* __restrict__ Out)
{
    extern __shared__ float sma[];
    float* Qs = sma;                  // 128 rows [m][w_perm]
    float* Ks = sma + 128 * KST;      // 64 rows  [key][w_perm]
    float* Vs = sma + 192 * KST;      // 64 rows  [w][key_perm]
    float* Ps = sma + 256 * KST;      // 128 rows [m][key_perm]

    const int tid = threadIdx.x;
    const int lane = tid & 31;
    const int wid = tid >> 5;
    const int lt = lane & 3;
    const int lgr = lane >> 2;
    const int mb = wid * 16;
    const int q0 = blockIdx.x * 128;
    const int h = blockIdx.y, b = blockIdx.z;

    const float* qb = g_q + (size_t)(b * H_ + h) * S_ * W_;
    const float* kb = g_k + (size_t)(b * H_ + h) * S_ * W_;
    const float* vb = g_vt + (size_t)(b * H_ + h) * W_ * S_;   // [W][S_perm]

    // P store slots (perm8 of key cols 2lt, 2lt+1)
    const int pA = 2 * ((2 * lt) & 3) + (((2 * lt) >> 2) & 1);
    const int pB = 2 * ((2 * lt + 1) & 3) + (((2 * lt + 1) >> 2) & 1);

    // Load Q tile once (already tf32 + scaled + permuted): plain copy
#pragma unroll
    for (int i = 0; i < 8; i++) {
        int u = i * 256 + tid;
        int r = u >> 4, c4 = (u & 15) * 4;
        *(float4*)&Qs[r * KST + c4] = *(const float4*)(qb + (size_t)(q0 + r) * W_ + c4);
    }

    float m0r = -INFINITY, m1r = -INFINITY, l0 = 0.0f, l1 = 0.0f;
    float oacc[8][4];
#pragma unroll
    for (int nb = 0; nb < 8; nb++)
#pragma unroll
        for (int j = 0; j < 4; j++) oacc[nb][j] = 0.0f;

    const int NT = S_ / 64;   // 32
    for (int j = 0; j < NT; j++) {
        const int j0 = j * 64;
        __syncthreads();   // prior reads of Ks/Vs done (also orders first Q fill)
#pragma unroll
        for (int i = 0; i < 4; i++) {
            int u = i * 256 + tid;
            int r = u >> 4, c4 = (u & 15) * 4;
            *(float4*)&Ks[r * KST + c4] = *(const float4*)(kb + (size_t)(j0 + r) * W_ + c4);
            *(float4*)&Vs[r * KST + c4] = *(const float4*)(vb + (size_t)r * S_ + j0 + c4);
        }
        __syncthreads();

        // S = Q @ K^T  (16 x 64 per warp)
        float sacc[8][4];
#pragma unroll
        for (int nb = 0; nb < 8; nb++)
#pragma unroll
            for (int j2 = 0; j2 < 4; j2++) sacc[nb][j2] = 0.0f;

#pragma unroll
        for (int ks = 0; ks < 8; ks++) {
            float2 a02 = *(const float2*)&Qs[(mb + lgr) * KST + ks * 8 + 2 * lt];
            float2 a13 = *(const float2*)&Qs[(mb + lgr + 8) * KST + ks * 8 + 2 * lt];
            uint32_t a[4] = {__float_as_uint(a02.x), __float_as_uint(a13.x),
                             __float_as_uint(a02.y), __float_as_uint(a13.y)};
#pragma unroll
            for (int nb = 0; nb < 8; nb++) {
                float2 b2 = *(const float2*)&Ks[(nb * 8 + lgr) * KST + ks * 8 + 2 * lt];
                uint32_t bfr[2] = {__float_as_uint(b2.x), __float_as_uint(b2.y)};
                mma_tf32(sacc[nb], a, bfr);
            }
        }

        // online softmax (rows lgr, lgr+8 of warp tile)
        float mx0 = -INFINITY, mx1 = -INFINITY;
#pragma unroll
        for (int nb = 0; nb < 8; nb++) {
            mx0 = fmaxf(mx0, fmaxf(sacc[nb][0], sacc[nb][1]));
            mx1 = fmaxf(mx1, fmaxf(sacc[nb][2], sacc[nb][3]));
        }
        mx0 = fmaxf(mx0, __shfl_xor_sync(0xffffffffu, mx0, 1));
        mx0 = fmaxf(mx0, __shfl_xor_sync(0xffffffffu, mx0, 2));
        mx1 = fmaxf(mx1, __shfl_xor_sync(0xffffffffu, mx1, 1));
        mx1 = fmaxf(mx1, __shfl_xor_sync(0xffffffffu, mx1, 2));

        float mn0 = fmaxf(m0r, mx0), mn1 = fmaxf(m1r, mx1);
        float al0 = __expf(m0r - mn0), al1 = __expf(m1r - mn1);
        float s0 = 0.0f, s1 = 0.0f;
#pragma unroll
        for (int nb = 0; nb < 8; nb++) {
            float p0 = __expf(sacc[nb][0] - mn0);
            float p1 = __expf(sacc[nb][1] - mn0);
            float p2 = __expf(sacc[nb][2] - mn1);
            float p3 = __expf(sacc[nb][3] - mn1);
            sacc[nb][0] = p0; sacc[nb][1] = p1; sacc[nb][2] = p2; sacc[nb][3] = p3;
            s0 += p0 + p1;
            s1 += p2 + p3;
        }
        s0 += __shfl_xor_sync(0xffffffffu, s0, 1);
        s0 += __shfl_xor_sync(0xffffffffu, s0, 2);
        s1 += __shfl_xor_sync(0xffffffffu, s1, 1);
        s1 += __shfl_xor_sync(0xffffffffu, s1, 2);
        l0 = l0 * al0 + s0;
        l1 = l1 * al1 + s1;
        m0r = mn0; m1r = mn1;
#pragma unroll
        for (int nb = 0; nb < 8; nb++) {
            oacc[nb][0] *= al0; oacc[nb][1] *= al0;
            oacc[nb][2] *= al1; oacc[nb][3] *= al1;
        }

        // stage P (tf32, perm8 key slots), warp-private rows
#pragma unroll
        for (int nb = 0; nb < 8; nb++) {
            Ps[(mb + lgr) * KST + nb * 8 + pA]     = tf32f(sacc[nb][0]);
            Ps[(mb + lgr) * KST + nb * 8 + pB]     = tf32f(sacc[nb][1]);
            Ps[(mb + lgr + 8) * KST + nb * 8 + pA] = tf32f(sacc[nb][2]);
            Ps[(mb + lgr + 8) * KST + nb * 8 + pB] = tf32f(sacc[nb][3]);
        }
        __syncwarp();

        // O += P @ V  (Vs = [w][key_perm])
#pragma unroll
        for (int ks = 0; ks < 8; ks++) {
            float2 a02 = *(const float2*)&Ps[(mb + lgr) * KST + ks * 8 + 2 * lt];
            float2 a13 = *(const float2*)&Ps[(mb + lgr + 8) * KST + ks * 8 + 2 * lt];
            uint32_t a[4] = {__float_as_uint(a02.x), __float_as_uint(a13.x),
                             __float_as_uint(a02.y), __float_as_uint(a13.y)};
#pragma unroll
            for (int nb = 0; nb < 8; nb++) {
                float2 b2 = *(const float2*)&Vs[(nb * 8 + lgr) * KST + ks * 8 + 2 * lt];
                uint32_t bfr[2] = {__float_as_uint(b2.x), __float_as_uint(b2.y)};
                mma_tf32(oacc[nb], a, bfr);
            }
        }
    }

    // epilogue: normalize, write [B,S,D]
    const float inv0 = 1.0f / l0, inv1 = 1.0f / l1;
    const int r0 = q0 + mb + lgr;
#pragma unroll
    for (int nb = 0; nb < 8; nb++) {
        int w = nb * 8 + lt * 2;
        float2 v0, v1;
        v0.x = oacc[nb][0] * inv0; v0.y = oacc[nb][1] * inv0;
        v1.x = oacc[nb][2] * inv1; v1.y = oacc[nb][3] * inv1;
        *(float2*)&Out[((size_t)b * S_ + r0) * D_ + h * W_ + w] = v0;
        *(float2*)&Out[((size_t)b * S_ + r0 + 8) * D_ + h * W_ + w] = v1;
    }
}

// ---------------------------------------------------------------------------
extern "C" void kernel_launch(void* const* d_in, const int* in_sizes, int n_in,
                              void* d_out, int out_size)
{
    const float* x  = (const float*)d_in[0];
    const float* Wq = (const float*)d_in[1];
    const float* bq = (const float*)d_in[2];
    const float* Wk = (const float*)d_in[3];
    const float* bk = (const float*)d_in[4];
    const float* Wv = (const float*)d_in[5];
    const float* bv = (const float*)d_in[6];
    float* out = (float*)d_out;

    float *pq, *pk, *pv, *pvt;
    cudaGetSymbolAddress((void**)&pq, g_q);
    cudaGetSymbolAddress((void**)&pk, g_k);
    cudaGetSymbolAddress((void**)&pv, g_v);
    cudaGetSymbolAddress((void**)&pvt, g_vt);

    const int gemm_smem = 2 * 2 * TBUF * (int)sizeof(float);
    dim3 ggrid(D_ / 128, M_ / 128, 3);
    qkv_gemm<<<ggrid, 256, gemm_smem>>>(x, Wq, Wk, Wv, bq, bk, bv, pq, pk, pv);

    dim3 tgrid(W_ / 32, S_ / 32, B_ * H_);   // (2, 64, 32)
    transpose_v<<<tgrid, 256>>>(pv, pvt);

    cudaFuncSetAttribute(attn_kernel, cudaFuncAttributeMaxDynamicSharedMemorySize, ATTN_SMEM);
    dim3 attn_grid(S_ / 128, H_, B_);        // (16, 16, 2)
    attn_kernel<<<attn_grid, 256, ATTN_SMEM>>>(out);
}